// round 14
// baseline (speedup 1.0000x reference)
#include <cuda_runtime.h>

// SeqSelfAttention (Bahdanau additive, windowed) — GB300 sm_103a
// B=4, L=1024, D=128, U=32, WIDTH=64, EPS=1e-7
//
// Algebra: unshifted softmax — |e| <= sum|Wa| ~ 4.5 so exp(e) in [1e-2, 90];
// dropping the max-shift changes only the +1e-7 denominator term by
// exp(-Mf): worst-case induced rel err ~1e-5 << 1e-3. ba cancels exactly.
// R14: barrier-free front end — kb loaded straight from L2 into registers
// (16 batched LDG.128, clamped+masked), q/Wa in warp-private smem slab
// (syncwarp only). The single __syncthreads (protecting xs for AV) moves
// AFTER softmax, hiding all xs staging under logit compute and letting
// warps/blocks desynchronize. qk + PDL frozen at R13.

#define LSEQ 1024
#define BB   4
#define DD   128
#define UU   32
#define TI   16
#define CW   80   // TI + 64
#define NROWS (BB*LSEQ)

__device__ float g_q [NROWS*UU];
__device__ float g_kb[NROWS*UU];

__device__ __forceinline__ float fast_tanh(float x){
    float y; asm("tanh.approx.f32 %0, %1;" : "=f"(y) : "f"(x)); return y;
}
__device__ __forceinline__ int iclamp(int v, int lo, int hi){
    return v < lo ? lo : (v > hi ? hi : v);
}

// ---------------------------------------------------------------------------
// Kernel 1: q = x @ Wt ; kb = x @ Wx + bh.  256 blocks x 128 thr,
// 16 rows/block, 4 rows/warp.  (R13 verbatim.)
// ---------------------------------------------------------------------------
#define QK_RPB 16
__global__ __launch_bounds__(128) void qk_kernel(
        const float* __restrict__ x,
        const float* __restrict__ Wt,
        const float* __restrict__ Wx,
        const float* __restrict__ bh)
{
    __shared__ float xs [QK_RPB*DD];    // 8 KB
    __shared__ float wts[DD*UU];        // 16 KB  [d][u]
    __shared__ float wxs[DD*UU];        // 16 KB
    const int t    = threadIdx.x;
    const int row0 = blockIdx.x * QK_RPB;

    {   // stage (all coalesced float4, layout-preserving)
        const float4* xg = (const float4*)(x + row0*DD);
        float4* xs4 = (float4*)xs;
        #pragma unroll
        for (int i = 0; i < 4; i++) xs4[t + i*128] = xg[t + i*128];
        const float4* wtg = (const float4*)Wt; float4* wt4 = (float4*)wts;
        const float4* wxg = (const float4*)Wx; float4* wx4 = (float4*)wxs;
        #pragma unroll
        for (int i = 0; i < 8; i++){
            wt4[t + i*128] = wtg[t + i*128];
            wx4[t + i*128] = wxg[t + i*128];
        }
    }
    __syncthreads();

    // Let the dependent attn kernel begin its (qk-independent) prologue.
    cudaTriggerProgrammaticLaunchCompletion();

    const int u  = t & 31;
    const int rg = t >> 5;
    const int rb = rg * 4;                 // 4 rows per warp
    float aq0=0,aq1=0,aq2=0,aq3=0, ak0=0,ak1=0,ak2=0,ak3=0;
    const float4* xs4 = (const float4*)xs;

    #pragma unroll 8
    for (int d4 = 0; d4 < 32; d4++){
        const int db = d4*4*32 + u;
        const float wt0 = wts[db], wt1 = wts[db+32], wt2 = wts[db+64], wt3 = wts[db+96];
        const float wx0 = wxs[db], wx1 = wxs[db+32], wx2 = wxs[db+64], wx3 = wxs[db+96];
        const float4 x0 = xs4[(rb+0)*32 + d4];   // broadcast LDS.128
        const float4 x1 = xs4[(rb+1)*32 + d4];
        const float4 x2 = xs4[(rb+2)*32 + d4];
        const float4 x3 = xs4[(rb+3)*32 + d4];
        aq0 += x0.x*wt0 + x0.y*wt1 + x0.z*wt2 + x0.w*wt3;
        aq1 += x1.x*wt0 + x1.y*wt1 + x1.z*wt2 + x1.w*wt3;
        aq2 += x2.x*wt0 + x2.y*wt1 + x2.z*wt2 + x2.w*wt3;
        aq3 += x3.x*wt0 + x3.y*wt1 + x3.z*wt2 + x3.w*wt3;
        ak0 += x0.x*wx0 + x0.y*wx1 + x0.z*wx2 + x0.w*wx3;
        ak1 += x1.x*wx0 + x1.y*wx1 + x1.z*wx2 + x1.w*wx3;
        ak2 += x2.x*wx0 + x2.y*wx1 + x2.z*wx2 + x2.w*wx3;
        ak3 += x3.x*wx0 + x3.y*wx1 + x3.z*wx2 + x3.w*wx3;
    }
    const float bhv = bh[u];
    const int r = row0 + rb;
    g_q [(r+0)*UU+u] = aq0;      g_q [(r+1)*UU+u] = aq1;
    g_q [(r+2)*UU+u] = aq2;      g_q [(r+3)*UU+u] = aq3;
    g_kb[(r+0)*UU+u] = ak0+bhv;  g_kb[(r+1)*UU+u] = ak1+bhv;
    g_kb[(r+2)*UU+u] = ak2+bhv;  g_kb[(r+3)*UU+u] = ak3+bhv;
}

// ---------------------------------------------------------------------------
// Kernel 2: windowed attention, barrier-free front end.
// grid (L/16, B) = 256 blocks, 256 thr. Warp w owns queries 2w, 2w+1.
// kb rows c0=2w+l, c1=c0+32 loaded DIRECTLY from g_kb (L2) into registers;
// q/Wa in a warp-private smem slab (syncwarp only). One __syncthreads,
// placed after softmax, protects xs for the AV phase.
// smem: xs[80][128] | 8 x warp slab{ q[64] | wa[32] | A[132] | pad[4] }
// ---------------------------------------------------------------------------
#define SLAB     232                        // floats per warp slab (16B mult)
#define OFF_WS   (CW*DD)                    // 10240
#define SMEM_FLOATS (OFF_WS + 8*SLAB)       // 12096 floats = 48384 B

extern __shared__ float smem[];

__global__ __launch_bounds__(256, 2) void attn_kernel(
        const float* __restrict__ x,
        const float* __restrict__ Wa,
        float* __restrict__ out)
{
    float* xs = smem;

    const int t    = threadIdx.x;
    const int i0   = blockIdx.x * TI;
    const int base = blockIdx.y * LSEQ;
    const int w    = t >> 5;
    const int l    = t & 31;

    float* slab = smem + OFF_WS + w*SLAB;   // q[0..63] wa[64..95] A[96..227]
    float* qsl  = slab;
    float* wasl = slab + 64;
    float* A    = slab + 96;

    // ---- phase 1 (qk-independent): stage xs[80][128] f4; stores in flight ----
    {
        float4* xs4 = (float4*)xs;
        const float4* xg4 = (const float4*)x;
        #pragma unroll
        for (int i = 0; i < 10; i++){
            const int idx = t + i*256;            // [0,2560) f4 of [80][32]
            const int c = idx >> 5, dq = idx & 31;
            const int j = i0 - 32 + c;
            float4 v = make_float4(0.f,0.f,0.f,0.f);
            if (j >= 0 && j < LSEQ) v = xg4[(base + j)*32 + dq];
            xs4[c*32 + dq] = v;
        }
    }

    // ---- wait for qk_kernel to fully complete (memory visible) ----
    cudaGridDependencySynchronize();

    // ---- warp-private stage: q (16 f4) + Wa (8 f4); syncwarp only ----
    {
        float4* qsl4 = (float4*)qsl;
        float4* wasl4 = (float4*)wasl;
        if (l < 16)
            qsl4[l] = ((const float4*)g_q)[(base + i0 + 2*w)*8 + l];
        else if (l < 24)
            wasl4[l - 16] = ((const float4*)Wa)[l - 16];
        __syncwarp();
    }

    const int c0 = 2*w + l, c1 = c0 + 32;
    const int j0 = i0 - 32 + c0;              // kA row's key index
    const int jO = i0 + 2*w + 32;             // orphan row's key index

    // ---- batch-load kb rows from global (L2) into registers, clamped ----
    float4 kA[8], kB[8];
    float kbO;
    {
        const float4* kAp = (const float4*)g_kb
                          + (base + iclamp(j0,      0, LSEQ-1))*8;
        const float4* kBp = (const float4*)g_kb
                          + (base + iclamp(j0 + 32, 0, LSEQ-1))*8;
        #pragma unroll
        for (int u4 = 0; u4 < 8; u4++) kA[u4] = kAp[u4];
        #pragma unroll
        for (int u4 = 0; u4 < 8; u4++) kB[u4] = kBp[u4];
        kbO = g_kb[(base + iclamp(jO, 0, LSEQ-1))*UU + l];
    }

    // ---- logits: kA/kB in registers, shared by q0 and q1 ----
    float e0a = 0.f, e0b = 0.f, e1a = 0.f, e1b = 0.f;
    {
        const float4* q0p = (const float4*)qsl;
        const float4* q1p = q0p + 8;
        const float4* wap = (const float4*)wasl;
        #pragma unroll
        for (int u4 = 0; u4 < 8; u4++){
            const float4 wa = wap[u4];            // broadcast LDS (warp slab)
            const float4 q0 = q0p[u4];            // broadcast LDS
            const float4 q1 = q1p[u4];
            e0a += wa.x*fast_tanh(q0.x+kA[u4].x) + wa.y*fast_tanh(q0.y+kA[u4].y)
                 + wa.z*fast_tanh(q0.z+kA[u4].z) + wa.w*fast_tanh(q0.w+kA[u4].w);
            e0b += wa.x*fast_tanh(q0.x+kB[u4].x) + wa.y*fast_tanh(q0.y+kB[u4].y)
                 + wa.z*fast_tanh(q0.z+kB[u4].z) + wa.w*fast_tanh(q0.w+kB[u4].w);
            e1a += wa.x*fast_tanh(q1.x+kA[u4].x) + wa.y*fast_tanh(q1.y+kA[u4].y)
                 + wa.z*fast_tanh(q1.z+kA[u4].z) + wa.w*fast_tanh(q1.w+kA[u4].w);
            e1b += wa.x*fast_tanh(q1.x+kB[u4].x) + wa.y*fast_tanh(q1.y+kB[u4].y)
                 + wa.z*fast_tanh(q1.z+kB[u4].z) + wa.w*fast_tanh(q1.w+kB[u4].w);
        }
    }

    // ---- orphan row (tile row 2w+64) for q1: u-parallel (lane = unit) ----
    float eo;
    {
        const float pv = wasl[l] * fast_tanh(qsl[32 + l] + kbO);
        eo = pv;
        #pragma unroll
        for (int o = 16; o; o >>= 1) eo += __shfl_xor_sync(0xffffffffu, eo, o);
        if (jO >= LSEQ) eo = -1e30f;              // warp-uniform mask
    }

    // ---- masks (exp(-1e30) -> 0) ----
    if (j0 < 0){ e0a = -1e30f; e1a = -1e30f; }
    if (j0 + 32 >= LSEQ){ e0b = -1e30f; e1b = -1e30f; }
    if (l == 0) e1a = -1e30f;                     // row 2w not in q1 window

    // ---- unshifted softmax: |e| <= ~5 so exp is safe; masked -> 0 ----
    float a0a, a0b, a1a, a1b, ao;
    {
        const float w0a = __expf(e0a), w0b = __expf(e0b);
        const float w1a = __expf(e1a), w1b = __expf(e1b);
        float s0 = w0a + w0b, s1 = w1a + w1b;
        #pragma unroll
        for (int o = 16; o; o >>= 1){
            s0 += __shfl_xor_sync(0xffffffffu, s0, o);
            s1 += __shfl_xor_sync(0xffffffffu, s1, o);
        }
        const float wo = __expf(eo);              // warp-uniform
        const float inv0 = 1.f / (s0 + 1e-7f);
        const float inv1 = 1.f / ((s1 + wo) + 1e-7f);
        a0a = w0a*inv0; a0b = w0b*inv0;
        a1a = w1a*inv1; a1b = w1b*inv1; ao = wo*inv1;
    }

    // ---- publish: slot k <-> row 2w+k ; (.x=q0, .y=q1) ----
    ((float2*)A)[l]      = make_float2(a0a, a1a);   // slots 0..31
    ((float2*)A)[l + 32] = make_float2(a0b, a1b);   // slots 32..63
    if (l == 0) ((float2*)A)[64] = make_float2(0.f, ao);   // orphan slot

    // ---- single block barrier: xs stores (phase 1) -> AV reads; also A ----
    __syncthreads();

    // ---- AV: 4 keys per chunk, 6 batched LDS.128 per 32 FFMA ----
    {
        const float4* xs4 = (const float4*)xs;
        const float4* A4  = (const float4*)A;     // pair j = slots 2j, 2j+1
        float4 acc0 = make_float4(0.f,0.f,0.f,0.f);
        float4 acc1 = make_float4(0.f,0.f,0.f,0.f);
        const int rb = 2*w;
        #pragma unroll
        for (int j = 0; j < 32; j += 2){
            const float4 ab0 = A4[j];                      // batched loads
            const float4 ab1 = A4[j+1];
            const float4 xv0 = xs4[(rb + 2*j    )*32 + l];
            const float4 xv1 = xs4[(rb + 2*j + 1)*32 + l];
            const float4 xv2 = xs4[(rb + 2*j + 2)*32 + l];
            const float4 xv3 = xs4[(rb + 2*j + 3)*32 + l];
            acc0.x += ab0.x*xv0.x; acc0.y += ab0.x*xv0.y;
            acc0.z += ab0.x*xv0.z; acc0.w += ab0.x*xv0.w;
            acc1.x += ab0.y*xv0.x; acc1.y += ab0.y*xv0.y;
            acc1.z += ab0.y*xv0.z; acc1.w += ab0.y*xv0.w;
            acc0.x += ab0.z*xv1.x; acc0.y += ab0.z*xv1.y;
            acc0.z += ab0.z*xv1.z; acc0.w += ab0.z*xv1.w;
            acc1.x += ab0.w*xv1.x; acc1.y += ab0.w*xv1.y;
            acc1.z += ab0.w*xv1.z; acc1.w += ab0.w*xv1.w;
            acc0.x += ab1.x*xv2.x; acc0.y += ab1.x*xv2.y;
            acc0.z += ab1.x*xv2.z; acc0.w += ab1.x*xv2.w;
            acc1.x += ab1.y*xv2.x; acc1.y += ab1.y*xv2.y;
            acc1.z += ab1.y*xv2.z; acc1.w += ab1.y*xv2.w;
            acc0.x += ab1.z*xv3.x; acc0.y += ab1.z*xv3.y;
            acc0.z += ab1.z*xv3.z; acc0.w += ab1.z*xv3.w;
            acc1.x += ab1.w*xv3.x; acc1.y += ab1.w*xv3.y;
            acc1.z += ab1.w*xv3.z; acc1.w += ab1.w*xv3.w;
        }
        {   // orphan key (row 2w+64): q1 only
            const float aov = A[129];                    // slot 64 .y
            const float4 xvo = xs4[(rb + 64)*32 + l];
            acc1.x += aov*xvo.x; acc1.y += aov*xvo.y;
            acc1.z += aov*xvo.z; acc1.w += aov*xvo.w;
        }
        float4* out4 = (float4*)out;
        out4[(base + i0 + rb    )*32 + l] = acc0;
        out4[(base + i0 + rb + 1)*32 + l] = acc1;
    }
}

// ---------------------------------------------------------------------------
extern "C" void kernel_launch(void* const* d_in, const int* in_sizes, int n_in,
                              void* d_out, int out_size)
{
    const float* x  = (const float*)d_in[0];
    const float* Wt = (const float*)d_in[1];
    const float* Wx = (const float*)d_in[2];
    const float* bh = (const float*)d_in[3];
    const float* Wa = (const float*)d_in[4];
    // d_in[5] = ba : cancels exactly in the (un)shifted softmax -> unused
    float* out = (float*)d_out;

    qk_kernel<<<NROWS/QK_RPB, 128>>>(x, Wt, Wx, bh);

    cudaFuncSetAttribute(attn_kernel,
                         cudaFuncAttributeMaxDynamicSharedMemorySize,
                         SMEM_FLOATS*4 + 256);

    // PDL launch: attn may start its prologue while qk runs; the
    // cudaGridDependencySynchronize() inside orders the g_q/g_kb reads.
    cudaLaunchConfig_t cfg = {};
    cfg.gridDim  = dim3(LSEQ/TI, BB, 1);
    cfg.blockDim = dim3(256, 1, 1);
    cfg.dynamicSmemBytes = SMEM_FLOATS*4;
    cfg.stream = 0;
    cudaLaunchAttribute at[1];
    at[0].id = cudaLaunchAttributeProgrammaticStreamSerialization;
    at[0].val.programmaticStreamSerializationAllowed = 1;
    cfg.attrs = at;
    cfg.numAttrs = 1;
    cudaLaunchKernelEx(&cfg, attn_kernel, x, Wa, out);
}

// round 15
// speedup vs baseline: 1.1045x; 1.1045x over previous
#include <cuda_runtime.h>

// SeqSelfAttention (Bahdanau additive, windowed) — GB300 sm_103a
// B=4, L=1024, D=128, U=32, WIDTH=64, EPS=1e-7
//
// Algebra: window-max softmax shift only perturbs the +1e-7 denominator by
// exp(Mw-Mfull) (rel err <~1e-6); ba cancels exactly.
// R15: single fused kernel. Phase 0 = qk for this block's own 16 rows
// (grid maps 1:1 onto qk's row tiles). Software grid barrier (all 256
// blocks co-resident: 2 blocks/SM x 152 SMs = 304 slots; two counters,
// release/acquire fences, last block resets both -> deterministic across
// graph replays). Phase 1 = R13 attn verbatim. Deletes the second launch
// + inter-kernel gap (~1.5us) for a ~0.3us in-kernel barrier.

#define LSEQ 1024
#define BB   4
#define DD   128
#define UU   32
#define TI   16
#define CW   80   // TI + 64
#define NROWS (BB*LSEQ)

__device__ float g_q [NROWS*UU];
__device__ float g_kb[NROWS*UU];
__device__ int   g_bar_cnt  = 0;
__device__ int   g_bar_done = 0;

__device__ __forceinline__ float fast_tanh(float x){
    float y; asm("tanh.approx.f32 %0, %1;" : "=f"(y) : "f"(x)); return y;
}

// ---------------------------------------------------------------------------
// smem layout (dynamic, aliased between phases):
// phase 0 (qk):   xsq[16][128] (8KB) | wts[128][32] (16KB) | wxs[128][32]
// phase 1 (attn): xs[80][128] | kbs[80][36] | qs[16][32] | was[32] | Aw[8][132]
// ---------------------------------------------------------------------------
#define KBS  36
#define OFF_KBS  (CW*DD)                   // 10240
#define OFF_QS   (OFF_KBS + CW*KBS)        // 13120
#define OFF_WAS  (OFF_QS + TI*UU)          // 13632
#define OFF_AW   (OFF_WAS + UU)            // 13664
#define SMEM_FLOATS (OFF_AW + 8*132)       // 14720 floats = 58880 B

extern __shared__ float smem[];

__global__ __launch_bounds__(256, 2) void fused_kernel(
        const float* __restrict__ x,
        const float* __restrict__ Wt,
        const float* __restrict__ Wx,
        const float* __restrict__ bh,
        const float* __restrict__ Wa,
        float* __restrict__ out)
{
    const int t    = threadIdx.x;
    const int i0   = blockIdx.x * TI;
    const int base = blockIdx.y * LSEQ;
    const int row0 = base + i0;            // this block's 16 qk rows

    // ================= phase 0: q/kb for rows row0..row0+15 ===============
    {
        float* xsq = smem;                 // [16][128]
        float* wts = smem + TI*DD;         // [128][32]
        float* wxs = wts + DD*UU;

        {   // stage (all coalesced float4, layout-preserving)
            const float4* xg = (const float4*)(x + row0*DD);
            float4* xs4 = (float4*)xsq;
            xs4[t] = xg[t];  xs4[t+256] = xg[t+256];
            const float4* wtg = (const float4*)Wt; float4* wt4 = (float4*)wts;
            const float4* wxg = (const float4*)Wx; float4* wx4 = (float4*)wxs;
            #pragma unroll
            for (int i = 0; i < 4; i++){
                wt4[t + i*256] = wtg[t + i*256];
                wx4[t + i*256] = wxg[t + i*256];
            }
        }
        __syncthreads();

        const int u  = t & 31;
        const int rg = t >> 5;
        const int r0 = rg * 2;             // 2 rows per warp
        float aq0=0,aq1=0, ak0=0,ak1=0;
        const float4* xs4 = (const float4*)xsq;

        #pragma unroll 8
        for (int d4 = 0; d4 < 32; d4++){
            const int db = d4*4*32 + u;
            const float wt0 = wts[db], wt1 = wts[db+32], wt2 = wts[db+64], wt3 = wts[db+96];
            const float wx0 = wxs[db], wx1 = wxs[db+32], wx2 = wxs[db+64], wx3 = wxs[db+96];
            const float4 x0 = xs4[(r0+0)*32 + d4];   // broadcast LDS.128
            const float4 x1 = xs4[(r0+1)*32 + d4];
            aq0 += x0.x*wt0 + x0.y*wt1 + x0.z*wt2 + x0.w*wt3;
            aq1 += x1.x*wt0 + x1.y*wt1 + x1.z*wt2 + x1.w*wt3;
            ak0 += x0.x*wx0 + x0.y*wx1 + x0.z*wx2 + x0.w*wx3;
            ak1 += x1.x*wx0 + x1.y*wx1 + x1.z*wx2 + x1.w*wx3;
        }
        const float bhv = bh[u];
        const int r = row0 + r0;
        g_q [(r+0)*UU+u] = aq0;      g_q [(r+1)*UU+u] = aq1;
        g_kb[(r+0)*UU+u] = ak0+bhv;  g_kb[(r+1)*UU+u] = ak1+bhv;
    }

    // ================= software grid barrier (256 blocks) =================
    __threadfence();                       // release g_q/g_kb stores
    __syncthreads();
    if (t == 0){
        atomicAdd(&g_bar_cnt, 1);
        while (atomicAdd(&g_bar_cnt, 0) < (int)(gridDim.x*gridDim.y)){
            __nanosleep(64);
        }
        __threadfence();                   // acquire other blocks' stores
        const int p = atomicAdd(&g_bar_done, 1);
        if (p == (int)(gridDim.x*gridDim.y) - 1){
            g_bar_cnt  = 0;                // all blocks past the spin:
            g_bar_done = 0;                // safe reset for next replay
            __threadfence();
        }
    }
    __syncthreads();

    // ================= phase 1: windowed attention (R13 verbatim) =========
    float* xs  = smem;
    float* kbs = smem + OFF_KBS;
    float* qs  = smem + OFF_QS;
    float* was = smem + OFF_WAS;
    float* Aw  = smem + OFF_AW;

    // ---- stage: xs[80][128] f4, kbs[80][36] f4, qs[16][32], was ----
    {
        float4* xs4 = (float4*)xs;
        const float4* xg4 = (const float4*)x;
        #pragma unroll
        for (int i = 0; i < 10; i++){
            const int idx = t + i*256;            // [0,2560) f4 of [80][32]
            const int c = idx >> 5, dq = idx & 31;
            const int j = i0 - 32 + c;
            float4 v = make_float4(0.f,0.f,0.f,0.f);
            if (j >= 0 && j < LSEQ) v = xg4[(base + j)*32 + dq];
            xs4[c*32 + dq] = v;
        }
        const float4* kg4 = (const float4*)g_kb;
        #pragma unroll
        for (int i = 0; i < 3; i++){
            const int idx = t + i*256;            // [0,640) f4 of [80][8]
            if (idx < 640){
                const int c = idx >> 3, u4 = idx & 7;
                const int j = i0 - 32 + c;
                float4 v = make_float4(0.f,0.f,0.f,0.f);
                if (j >= 0 && j < LSEQ) v = kg4[(base + j)*8 + u4];
                ((float4*)(kbs + c*KBS))[u4] = v;
            }
        }
        if (t < 128) ((float4*)qs)[t] = ((const float4*)(g_q + row0*UU))[t];
        if (t < 32) was[t] = Wa[t];
    }
    __syncthreads();

    const int w = t >> 5;
    const int l = t & 31;
    const int c0 = 2*w + l, c1 = c0 + 32;

    // ---- batch-load the lane's full kb working set (16 indep LDS.128) ----
    float4 kA[8], kB[8];
    {
        const float4* kAp = (const float4*)(kbs + c0*KBS);
        const float4* kBp = (const float4*)(kbs + c1*KBS);
        #pragma unroll
        for (int u4 = 0; u4 < 8; u4++) kA[u4] = kAp[u4];
        #pragma unroll
        for (int u4 = 0; u4 < 8; u4++) kB[u4] = kBp[u4];
    }

    // ---- logits: kA/kB in registers, shared by q0 and q1 ----
    float e0a = 0.f, e0b = 0.f, e1a = 0.f, e1b = 0.f;
    {
        const float4* q0p = (const float4*)(qs + 2*w*UU);
        const float4* q1p = q0p + 8;
        const float4* wap = (const float4*)was;
        #pragma unroll
        for (int u4 = 0; u4 < 8; u4++){
            const float4 wa = wap[u4];            // broadcast
            const float4 q0 = q0p[u4];            // broadcast
            const float4 q1 = q1p[u4];
            e0a += wa.x*fast_tanh(q0.x+kA[u4].x) + wa.y*fast_tanh(q0.y+kA[u4].y)
                 + wa.z*fast_tanh(q0.z+kA[u4].z) + wa.w*fast_tanh(q0.w+kA[u4].w);
            e0b += wa.x*fast_tanh(q0.x+kB[u4].x) + wa.y*fast_tanh(q0.y+kB[u4].y)
                 + wa.z*fast_tanh(q0.z+kB[u4].z) + wa.w*fast_tanh(q0.w+kB[u4].w);
            e1a += wa.x*fast_tanh(q1.x+kA[u4].x) + wa.y*fast_tanh(q1.y+kA[u4].y)
                 + wa.z*fast_tanh(q1.z+kA[u4].z) + wa.w*fast_tanh(q1.w+kA[u4].w);
            e1b += wa.x*fast_tanh(q1.x+kB[u4].x) + wa.y*fast_tanh(q1.y+kB[u4].y)
                 + wa.z*fast_tanh(q1.z+kB[u4].z) + wa.w*fast_tanh(q1.w+kB[u4].w);
        }
    }

    // ---- orphan row 2w+64 for q1: u-parallel (lane = unit) ----
    float eo;
    {
        const float pv = was[l] * fast_tanh(qs[(2*w+1)*UU + l]
                                          + kbs[(2*w+64)*KBS + l]);
        eo = pv;
        #pragma unroll
        for (int o = 16; o; o >>= 1) eo += __shfl_xor_sync(0xffffffffu, eo, o);
        if (i0 + 2*w + 32 >= LSEQ) eo = -1e30f;   // warp-uniform mask
    }

    // ---- masks ----
    {
        const int j0 = i0 - 32 + c0;              // kA row's key index
        if (j0 < 0){ e0a = -1e30f; e1a = -1e30f; }
        if (j0 + 32 >= LSEQ){ e0b = -1e30f; e1b = -1e30f; }
        if (l == 0) e1a = -1e30f;                 // row 2w not in q1 window
    }

    // ---- two warp softmaxes (q1 includes orphan term) ----
    float a0a, a0b, a1a, a1b, ao;
    {
        float m0 = fmaxf(e0a, e0b), m1 = fmaxf(e1a, e1b);
        #pragma unroll
        for (int o = 16; o; o >>= 1){
            m0 = fmaxf(m0, __shfl_xor_sync(0xffffffffu, m0, o));
            m1 = fmaxf(m1, __shfl_xor_sync(0xffffffffu, m1, o));
        }
        const float M1 = fmaxf(m1, eo);
        const float w0a = __expf(e0a - m0), w0b = __expf(e0b - m0);
        const float w1a = __expf(e1a - M1), w1b = __expf(e1b - M1);
        float s0 = w0a + w0b, s1 = w1a + w1b;
        #pragma unroll
        for (int o = 16; o; o >>= 1){
            s0 += __shfl_xor_sync(0xffffffffu, s0, o);
            s1 += __shfl_xor_sync(0xffffffffu, s1, o);
        }
        const float wo = __expf(eo - M1);         // warp-uniform
        const float inv0 = 1.f / (s0 + 1e-7f);
        const float inv1 = 1.f / ((s1 + wo) + 1e-7f);
        a0a = w0a*inv0; a0b = w0b*inv0;
        a1a = w1a*inv1; a1b = w1b*inv1; ao = wo*inv1;
    }

    // ---- publish: slot k <-> row 2w+k ; (.x=q0, .y=q1) ----
    float* A = Aw + w*132;
    ((float2*)A)[l]      = make_float2(a0a, a1a);   // slots 0..31
    ((float2*)A)[l + 32] = make_float2(a0b, a1b);   // slots 32..63
    if (l == 0) ((float2*)A)[64] = make_float2(0.f, ao);   // orphan slot
    __syncwarp();

    // ---- AV: 4 keys per chunk, 6 batched LDS.128 per 32 FFMA ----
    {
        const float4* xs4 = (const float4*)xs;
        const float4* A4  = (const float4*)A;     // pair j = slots 2j, 2j+1
        float4 acc0 = make_float4(0.f,0.f,0.f,0.f);
        float4 acc1 = make_float4(0.f,0.f,0.f,0.f);
        const int rb = 2*w;
        #pragma unroll
        for (int j = 0; j < 32; j += 2){
            const float4 ab0 = A4[j];                      // batched loads
            const float4 ab1 = A4[j+1];
            const float4 xv0 = xs4[(rb + 2*j    )*32 + l];
            const float4 xv1 = xs4[(rb + 2*j + 1)*32 + l];
            const float4 xv2 = xs4[(rb + 2*j + 2)*32 + l];
            const float4 xv3 = xs4[(rb + 2*j + 3)*32 + l];
            acc0.x += ab0.x*xv0.x; acc0.y += ab0.x*xv0.y;
            acc0.z += ab0.x*xv0.z; acc0.w += ab0.x*xv0.w;
            acc1.x += ab0.y*xv0.x; acc1.y += ab0.y*xv0.y;
            acc1.z += ab0.y*xv0.z; acc1.w += ab0.y*xv0.w;
            acc0.x += ab0.z*xv1.x; acc0.y += ab0.z*xv1.y;
            acc0.z += ab0.z*xv1.z; acc0.w += ab0.z*xv1.w;
            acc1.x += ab0.w*xv1.x; acc1.y += ab0.w*xv1.y;
            acc1.z += ab0.w*xv1.z; acc1.w += ab0.w*xv1.w;
            acc0.x += ab1.x*xv2.x; acc0.y += ab1.x*xv2.y;
            acc0.z += ab1.x*xv2.z; acc0.w += ab1.x*xv2.w;
            acc1.x += ab1.y*xv2.x; acc1.y += ab1.y*xv2.y;
            acc1.z += ab1.y*xv2.z; acc1.w += ab1.y*xv2.w;
            acc0.x += ab1.z*xv3.x; acc0.y += ab1.z*xv3.y;
            acc0.z += ab1.z*xv3.z; acc0.w += ab1.z*xv3.w;
            acc1.x += ab1.w*xv3.x; acc1.y += ab1.w*xv3.y;
            acc1.z += ab1.w*xv3.z; acc1.w += ab1.w*xv3.w;
        }
        {   // orphan key (row 2w+64): q1 only
            const float aov = A[129];                    // slot 64 .y
            const float4 xvo = xs4[(rb + 64)*32 + l];
            acc1.x += aov*xvo.x; acc1.y += aov*xvo.y;
            acc1.z += aov*xvo.z; acc1.w += aov*xvo.w;
        }
        float4* out4 = (float4*)out;
        out4[(base + i0 + rb    )*32 + l] = acc0;
        out4[(base + i0 + rb + 1)*32 + l] = acc1;
    }
}

// ---------------------------------------------------------------------------
extern "C" void kernel_launch(void* const* d_in, const int* in_sizes, int n_in,
                              void* d_out, int out_size)
{
    const float* x  = (const float*)d_in[0];
    const float* Wt = (const float*)d_in[1];
    const float* Wx = (const float*)d_in[2];
    const float* bh = (const float*)d_in[3];
    const float* Wa = (const float*)d_in[4];
    // d_in[5] = ba : cancels exactly in the shifted softmax -> unused
    float* out = (float*)d_out;

    cudaFuncSetAttribute(fused_kernel,
                         cudaFuncAttributeMaxDynamicSharedMemorySize,
                         SMEM_FLOATS*4 + 256);
    dim3 grid(LSEQ/TI, BB);
    fused_kernel<<<grid, 256, SMEM_FLOATS*4>>>(x, Wt, Wx, bh, Wa, out);
}

// round 16
// speedup vs baseline: 1.1086x; 1.0037x over previous
#include <cuda_runtime.h>

// SeqSelfAttention (Bahdanau additive, windowed) — GB300 sm_103a
// B=4, L=1024, D=128, U=32, WIDTH=64, EPS=1e-7
//
// Algebra: window-max softmax shift only perturbs the +1e-7 denominator by
// exp(Mw-Mfull) (rel err <~1e-6); ba cancels exactly.
// R16: q-GEMM folded into attn as a warp-local step (warp w computes q rows
// 2w,2w+1 from staged Wt + resident xs; no extra barrier) — attn has idle
// issue slots (36%) and has absorbed every instruction-count change so far.
// Kernel 1 now computes ONLY kb: half the FMA/staging (~1.2us). PDL kept.

#define LSEQ 1024
#define BB   4
#define DD   128
#define UU   32
#define TI   16
#define CW   80   // TI + 64
#define NROWS (BB*LSEQ)

__device__ float g_kb[NROWS*UU];

__device__ __forceinline__ float fast_tanh(float x){
    float y; asm("tanh.approx.f32 %0, %1;" : "=f"(y) : "f"(x)); return y;
}

// ---------------------------------------------------------------------------
// Kernel 1: kb = x @ Wx + bh.  256 blocks x 128 thr, 16 rows/block,
// 4 rows/warp. (R13 qk structure, Wt half deleted.)
// ---------------------------------------------------------------------------
#define QK_RPB 16
__global__ __launch_bounds__(128) void kb_kernel(
        const float* __restrict__ x,
        const float* __restrict__ Wx,
        const float* __restrict__ bh)
{
    __shared__ float xs [QK_RPB*DD];    // 8 KB
    __shared__ float wxs[DD*UU];        // 16 KB  [d][u]
    const int t    = threadIdx.x;
    const int row0 = blockIdx.x * QK_RPB;

    {   // stage (all coalesced float4, layout-preserving)
        const float4* xg = (const float4*)(x + row0*DD);
        float4* xs4 = (float4*)xs;
        #pragma unroll
        for (int i = 0; i < 4; i++) xs4[t + i*128] = xg[t + i*128];
        const float4* wxg = (const float4*)Wx; float4* wx4 = (float4*)wxs;
        #pragma unroll
        for (int i = 0; i < 8; i++) wx4[t + i*128] = wxg[t + i*128];
    }
    __syncthreads();

    // Let the dependent attn kernel begin its (kb-independent) prologue.
    cudaTriggerProgrammaticLaunchCompletion();

    const int u  = t & 31;
    const int rg = t >> 5;
    const int rb = rg * 4;                 // 4 rows per warp
    float ak0=0,ak1=0,ak2=0,ak3=0;
    const float4* xs4 = (const float4*)xs;

    #pragma unroll 8
    for (int d4 = 0; d4 < 32; d4++){
        const int db = d4*4*32 + u;
        const float wx0 = wxs[db], wx1 = wxs[db+32], wx2 = wxs[db+64], wx3 = wxs[db+96];
        const float4 x0 = xs4[(rb+0)*32 + d4];   // broadcast LDS.128
        const float4 x1 = xs4[(rb+1)*32 + d4];
        const float4 x2 = xs4[(rb+2)*32 + d4];
        const float4 x3 = xs4[(rb+3)*32 + d4];
        ak0 += x0.x*wx0 + x0.y*wx1 + x0.z*wx2 + x0.w*wx3;
        ak1 += x1.x*wx0 + x1.y*wx1 + x1.z*wx2 + x1.w*wx3;
        ak2 += x2.x*wx0 + x2.y*wx1 + x2.z*wx2 + x2.w*wx3;
        ak3 += x3.x*wx0 + x3.y*wx1 + x3.z*wx2 + x3.w*wx3;
    }
    const float bhv = bh[u];
    const int r = row0 + rb;
    g_kb[(r+0)*UU+u] = ak0+bhv;  g_kb[(r+1)*UU+u] = ak1+bhv;
    g_kb[(r+2)*UU+u] = ak2+bhv;  g_kb[(r+3)*UU+u] = ak3+bhv;
}

// ---------------------------------------------------------------------------
// Kernel 2: windowed attention + fused q-GEMM.
// grid (L/16, B) = 256 blocks, 256 thr. Warp w owns queries 2w, 2w+1:
// it COMPUTES their q rows locally (lane = u) from staged Wt and the
// already-resident xs rows (tile rows 32+2w, 33+2w), then proceeds with the
// R13 logit/softmax/AV pipeline (kb via smem, register-batched).
// smem: xs[80][128] | kbs[80][36] | qs[16][32] | was[32] | Aw[8][132]
//       | wts[128][32]
// ---------------------------------------------------------------------------
#define KBS  36
#define OFF_KBS  (CW*DD)                   // 10240
#define OFF_QS   (OFF_KBS + CW*KBS)        // 13120
#define OFF_WAS  (OFF_QS + TI*UU)          // 13632
#define OFF_AW   (OFF_WAS + UU)            // 13664
#define OFF_WT   (OFF_AW + 8*132)          // 14720
#define SMEM_FLOATS (OFF_WT + DD*UU)       // 18816 floats = 75264 B

extern __shared__ float smem[];

__global__ __launch_bounds__(256, 2) void attn_kernel(
        const float* __restrict__ x,
        const float* __restrict__ Wt,
        const float* __restrict__ Wa,
        float* __restrict__ out)
{
    float* xs  = smem;
    float* kbs = smem + OFF_KBS;
    float* qs  = smem + OFF_QS;
    float* was = smem + OFF_WAS;
    float* Aw  = smem + OFF_AW;
    float* wts = smem + OFF_WT;

    const int t    = threadIdx.x;
    const int i0   = blockIdx.x * TI;
    const int base = blockIdx.y * LSEQ;

    // ---- phase 1 (kb-independent): stage xs[80][128], Wt[128][32], Wa ----
    {
        float4* xs4 = (float4*)xs;
        const float4* xg4 = (const float4*)x;
        #pragma unroll
        for (int i = 0; i < 10; i++){
            const int idx = t + i*256;            // [0,2560) f4 of [80][32]
            const int c = idx >> 5, dq = idx & 31;
            const int j = i0 - 32 + c;
            float4 v = make_float4(0.f,0.f,0.f,0.f);
            if (j >= 0 && j < LSEQ) v = xg4[(base + j)*32 + dq];
            xs4[c*32 + dq] = v;
        }
        const float4* wtg = (const float4*)Wt;
        float4* wt4 = (float4*)wts;
        #pragma unroll
        for (int i = 0; i < 4; i++) wt4[t + i*256] = wtg[t + i*256];
        if (t < 32) was[t] = Wa[t];
    }

    // ---- wait for kb_kernel to fully complete (memory visible) ----
    cudaGridDependencySynchronize();

    // ---- phase 2: stage kbs[80][36] f4 from kb output ----
    {
        const float4* kg4 = (const float4*)g_kb;
        #pragma unroll
        for (int i = 0; i < 3; i++){
            const int idx = t + i*256;            // [0,640) f4 of [80][8]
            if (idx < 640){
                const int c = idx >> 3, u4 = idx & 7;
                const int j = i0 - 32 + c;
                float4 v = make_float4(0.f,0.f,0.f,0.f);
                if (j >= 0 && j < LSEQ) v = kg4[(base + j)*8 + u4];
                ((float4*)(kbs + c*KBS))[u4] = v;
            }
        }
    }
    __syncthreads();

    const int w = t >> 5;
    const int l = t & 31;
    const int c0 = 2*w + l, c1 = c0 + 32;

    // ---- fused q-GEMM: warp w computes q rows 2w, 2w+1 (lane = unit) ----
    {
        float aq0 = 0.f, aq1 = 0.f;
        const float4* x0p = (const float4*)(xs + (32 + 2*w)*DD);  // own row
        const float4* x1p = x0p + 32;
        #pragma unroll 8
        for (int d4 = 0; d4 < 32; d4++){
            const int db = d4*4*32 + l;
            const float w0 = wts[db], w1 = wts[db+32];    // conflict-free
            const float w2 = wts[db+64], w3 = wts[db+96];
            const float4 x0 = x0p[d4];                    // broadcast LDS.128
            const float4 x1 = x1p[d4];
            aq0 += x0.x*w0 + x0.y*w1 + x0.z*w2 + x0.w*w3;
            aq1 += x1.x*w0 + x1.y*w1 + x1.z*w2 + x1.w*w3;
        }
        qs[(2*w    )*UU + l] = aq0;      // warp-private slab of qs
        qs[(2*w + 1)*UU + l] = aq1;
        __syncwarp();
    }

    // ---- batch-load the lane's full kb working set (16 indep LDS.128) ----
    float4 kA[8], kB[8];
    {
        const float4* kAp = (const float4*)(kbs + c0*KBS);
        const float4* kBp = (const float4*)(kbs + c1*KBS);
        #pragma unroll
        for (int u4 = 0; u4 < 8; u4++) kA[u4] = kAp[u4];
        #pragma unroll
        for (int u4 = 0; u4 < 8; u4++) kB[u4] = kBp[u4];
    }

    // ---- logits: kA/kB in registers, shared by q0 and q1 ----
    float e0a = 0.f, e0b = 0.f, e1a = 0.f, e1b = 0.f;
    {
        const float4* q0p = (const float4*)(qs + 2*w*UU);
        const float4* q1p = q0p + 8;
        const float4* wap = (const float4*)was;
        #pragma unroll
        for (int u4 = 0; u4 < 8; u4++){
            const float4 wa = wap[u4];            // broadcast
            const float4 q0 = q0p[u4];            // broadcast
            const float4 q1 = q1p[u4];
            e0a += wa.x*fast_tanh(q0.x+kA[u4].x) + wa.y*fast_tanh(q0.y+kA[u4].y)
                 + wa.z*fast_tanh(q0.z+kA[u4].z) + wa.w*fast_tanh(q0.w+kA[u4].w);
            e0b += wa.x*fast_tanh(q0.x+kB[u4].x) + wa.y*fast_tanh(q0.y+kB[u4].y)
                 + wa.z*fast_tanh(q0.z+kB[u4].z) + wa.w*fast_tanh(q0.w+kB[u4].w);
            e1a += wa.x*fast_tanh(q1.x+kA[u4].x) + wa.y*fast_tanh(q1.y+kA[u4].y)
                 + wa.z*fast_tanh(q1.z+kA[u4].z) + wa.w*fast_tanh(q1.w+kA[u4].w);
            e1b += wa.x*fast_tanh(q1.x+kB[u4].x) + wa.y*fast_tanh(q1.y+kB[u4].y)
                 + wa.z*fast_tanh(q1.z+kB[u4].z) + wa.w*fast_tanh(q1.w+kB[u4].w);
        }
    }

    // ---- orphan row 2w+64 for q1: u-parallel (lane = unit) ----
    float eo;
    {
        const float pv = was[l] * fast_tanh(qs[(2*w+1)*UU + l]
                                          + kbs[(2*w+64)*KBS + l]);
        eo = pv;
        #pragma unroll
        for (int o = 16; o; o >>= 1) eo += __shfl_xor_sync(0xffffffffu, eo, o);
        if (i0 + 2*w + 32 >= LSEQ) eo = -1e30f;   // warp-uniform mask
    }

    // ---- masks ----
    {
        const int j0 = i0 - 32 + c0;              // kA row's key index
        if (j0 < 0){ e0a = -1e30f; e1a = -1e30f; }
        if (j0 + 32 >= LSEQ){ e0b = -1e30f; e1b = -1e30f; }
        if (l == 0) e1a = -1e30f;                 // row 2w not in q1 window
    }

    // ---- two warp softmaxes (q1 includes orphan term) ----
    float a0a, a0b, a1a, a1b, ao;
    {
        float m0 = fmaxf(e0a, e0b), m1 = fmaxf(e1a, e1b);
        #pragma unroll
        for (int o = 16; o; o >>= 1){
            m0 = fmaxf(m0, __shfl_xor_sync(0xffffffffu, m0, o));
            m1 = fmaxf(m1, __shfl_xor_sync(0xffffffffu, m1, o));
        }
        const float M1 = fmaxf(m1, eo);
        const float w0a = __expf(e0a - m0), w0b = __expf(e0b - m0);
        const float w1a = __expf(e1a - M1), w1b = __expf(e1b - M1);
        float s0 = w0a + w0b, s1 = w1a + w1b;
        #pragma unroll
        for (int o = 16; o; o >>= 1){
            s0 += __shfl_xor_sync(0xffffffffu, s0, o);
            s1 += __shfl_xor_sync(0xffffffffu, s1, o);
        }
        const float wo = __expf(eo - M1);         // warp-uniform
        const float inv0 = 1.f / (s0 + 1e-7f);
        const float inv1 = 1.f / ((s1 + wo) + 1e-7f);
        a0a = w0a*inv0; a0b = w0b*inv0;
        a1a = w1a*inv1; a1b = w1b*inv1; ao = wo*inv1;
    }

    // ---- publish: slot k <-> row 2w+k ; (.x=q0, .y=q1) ----
    float* A = Aw + w*132;
    ((float2*)A)[l]      = make_float2(a0a, a1a);   // slots 0..31
    ((float2*)A)[l + 32] = make_float2(a0b, a1b);   // slots 32..63
    if (l == 0) ((float2*)A)[64] = make_float2(0.f, ao);   // orphan slot
    __syncwarp();

    // ---- AV: 4 keys per chunk, 6 batched LDS.128 per 32 FFMA ----
    {
        const float4* xs4 = (const float4*)xs;
        const float4* A4  = (const float4*)A;     // pair j = slots 2j, 2j+1
        float4 acc0 = make_float4(0.f,0.f,0.f,0.f);
        float4 acc1 = make_float4(0.f,0.f,0.f,0.f);
        const int rb = 2*w;
        #pragma unroll
        for (int j = 0; j < 32; j += 2){
            const float4 ab0 = A4[j];                      // batched loads
            const float4 ab1 = A4[j+1];
            const float4 xv0 = xs4[(rb + 2*j    )*32 + l];
            const float4 xv1 = xs4[(rb + 2*j + 1)*32 + l];
            const float4 xv2 = xs4[(rb + 2*j + 2)*32 + l];
            const float4 xv3 = xs4[(rb + 2*j + 3)*32 + l];
            acc0.x += ab0.x*xv0.x; acc0.y += ab0.x*xv0.y;
            acc0.z += ab0.x*xv0.z; acc0.w += ab0.x*xv0.w;
            acc1.x += ab0.y*xv0.x; acc1.y += ab0.y*xv0.y;
            acc1.z += ab0.y*xv0.z; acc1.w += ab0.y*xv0.w;
            acc0.x += ab0.z*xv1.x; acc0.y += ab0.z*xv1.y;
            acc0.z += ab0.z*xv1.z; acc0.w += ab0.z*xv1.w;
            acc1.x += ab0.w*xv1.x; acc1.y += ab0.w*xv1.y;
            acc1.z += ab0.w*xv1.z; acc1.w += ab0.w*xv1.w;
            acc0.x += ab1.x*xv2.x; acc0.y += ab1.x*xv2.y;
            acc0.z += ab1.x*xv2.z; acc0.w += ab1.x*xv2.w;
            acc1.x += ab1.y*xv2.x; acc1.y += ab1.y*xv2.y;
            acc1.z += ab1.y*xv2.z; acc1.w += ab1.y*xv2.w;
            acc0.x += ab1.z*xv3.x; acc0.y += ab1.z*xv3.y;
            acc0.z += ab1.z*xv3.z; acc0.w += ab1.z*xv3.w;
            acc1.x += ab1.w*xv3.x; acc1.y += ab1.w*xv3.y;
            acc1.z += ab1.w*xv3.z; acc1.w += ab1.w*xv3.w;
        }
        {   // orphan key (row 2w+64): q1 only
            const float aov = A[129];                    // slot 64 .y
            const float4 xvo = xs4[(rb + 64)*32 + l];
            acc1.x += aov*xvo.x; acc1.y += aov*xvo.y;
            acc1.z += aov*xvo.z; acc1.w += aov*xvo.w;
        }
        float4* out4 = (float4*)out;
        out4[(base + i0 + rb    )*32 + l] = acc0;
        out4[(base + i0 + rb + 1)*32 + l] = acc1;
    }
}

// ---------------------------------------------------------------------------
extern "C" void kernel_launch(void* const* d_in, const int* in_sizes, int n_in,
                              void* d_out, int out_size)
{
    const float* x  = (const float*)d_in[0];
    const float* Wt = (const float*)d_in[1];
    const float* Wx = (const float*)d_in[2];
    const float* bh = (const float*)d_in[3];
    const float* Wa = (const float*)d_in[4];
    // d_in[5] = ba : cancels exactly in the shifted softmax -> unused
    float* out = (float*)d_out;

    kb_kernel<<<NROWS/QK_RPB, 128>>>(x, Wx, bh);

    cudaFuncSetAttribute(attn_kernel,
                         cudaFuncAttributeMaxDynamicSharedMemorySize,
                         SMEM_FLOATS*4 + 256);

    // PDL launch: attn may start its prologue while kb_kernel runs; the
    // cudaGridDependencySynchronize() inside orders the g_kb reads.
    cudaLaunchConfig_t cfg = {};
    cfg.gridDim  = dim3(LSEQ/TI, BB, 1);
    cfg.blockDim = dim3(256, 1, 1);
    cfg.dynamicSmemBytes = SMEM_FLOATS*4;
    cfg.stream = 0;
    cudaLaunchAttribute at[1];
    at[0].id = cudaLaunchAttributeProgrammaticStreamSerialization;
    at[0].val.programmaticStreamSerializationAllowed = 1;
    cfg.attrs = at;
    cfg.numAttrs = 1;
    cudaLaunchKernelEx(&cfg, attn_kernel, x, Wt, Wa, out);
}

// round 17
// speedup vs baseline: 1.2814x; 1.1558x over previous
#include <cuda_runtime.h>

// SeqSelfAttention (Bahdanau additive, windowed) — GB300 sm_103a
// B=4, L=1024, D=128, U=32, WIDTH=64, EPS=1e-7
//
// Algebra: window-max softmax shift only perturbs the +1e-7 denominator by
// exp(Mw-Mfull) (rel err <~1e-6); ba cancels exactly.
// R17 (FINAL): R13 verbatim — the converged optimum (14.816us, reproduced
// 3x). qk: 256 blocks x 128 thr, 16 rows/block, 4 rows/warp, PDL trigger.
// attn: 2 queries/warp with register-batched kb working set (MLP 16),
// orphan-row fold, 4-key AV chunks, lb(256,2); PDL-split staging.
// Measured-negative directions (do not revisit): split-KV merge, f32x2
// packing, direct-LDG kb, grid-barrier fusion, q-GEMM refolding.

#define LSEQ 1024
#define BB   4
#define DD   128
#define UU   32
#define TI   16
#define CW   80   // TI + 64
#define NROWS (BB*LSEQ)

__device__ float g_q [NROWS*UU];
__device__ float g_kb[NROWS*UU];

__device__ __forceinline__ float fast_tanh(float x){
    float y; asm("tanh.approx.f32 %0, %1;" : "=f"(y) : "f"(x)); return y;
}

// ---------------------------------------------------------------------------
// Kernel 1: q = x @ Wt ; kb = x @ Wx + bh.  256 blocks x 128 thr,
// 16 rows/block, 4 rows/warp. W in natural [d][u] layout (f4-coalesced
// stage, conflict-free scalar reads: lane = u).
// ---------------------------------------------------------------------------
#define QK_RPB 16
__global__ __launch_bounds__(128) void qk_kernel(
        const float* __restrict__ x,
        const float* __restrict__ Wt,
        const float* __restrict__ Wx,
        const float* __restrict__ bh)
{
    __shared__ float xs [QK_RPB*DD];    // 8 KB
    __shared__ float wts[DD*UU];        // 16 KB  [d][u]
    __shared__ float wxs[DD*UU];        // 16 KB
    const int t    = threadIdx.x;
    const int row0 = blockIdx.x * QK_RPB;

    {   // stage (all coalesced float4, layout-preserving)
        const float4* xg = (const float4*)(x + row0*DD);
        float4* xs4 = (float4*)xs;
        #pragma unroll
        for (int i = 0; i < 4; i++) xs4[t + i*128] = xg[t + i*128];
        const float4* wtg = (const float4*)Wt; float4* wt4 = (float4*)wts;
        const float4* wxg = (const float4*)Wx; float4* wx4 = (float4*)wxs;
        #pragma unroll
        for (int i = 0; i < 8; i++){
            wt4[t + i*128] = wtg[t + i*128];
            wx4[t + i*128] = wxg[t + i*128];
        }
    }
    __syncthreads();

    // Let the dependent attn kernel begin its (qk-independent) prologue.
    cudaTriggerProgrammaticLaunchCompletion();

    const int u  = t & 31;
    const int rg = t >> 5;
    const int rb = rg * 4;                 // 4 rows per warp
    float aq0=0,aq1=0,aq2=0,aq3=0, ak0=0,ak1=0,ak2=0,ak3=0;
    const float4* xs4 = (const float4*)xs;

    #pragma unroll 8
    for (int d4 = 0; d4 < 32; d4++){
        const int db = d4*4*32 + u;
        const float wt0 = wts[db], wt1 = wts[db+32], wt2 = wts[db+64], wt3 = wts[db+96];
        const float wx0 = wxs[db], wx1 = wxs[db+32], wx2 = wxs[db+64], wx3 = wxs[db+96];
        const float4 x0 = xs4[(rb+0)*32 + d4];   // broadcast LDS.128
        const float4 x1 = xs4[(rb+1)*32 + d4];
        const float4 x2 = xs4[(rb+2)*32 + d4];
        const float4 x3 = xs4[(rb+3)*32 + d4];
        aq0 += x0.x*wt0 + x0.y*wt1 + x0.z*wt2 + x0.w*wt3;
        aq1 += x1.x*wt0 + x1.y*wt1 + x1.z*wt2 + x1.w*wt3;
        aq2 += x2.x*wt0 + x2.y*wt1 + x2.z*wt2 + x2.w*wt3;
        aq3 += x3.x*wt0 + x3.y*wt1 + x3.z*wt2 + x3.w*wt3;
        ak0 += x0.x*wx0 + x0.y*wx1 + x0.z*wx2 + x0.w*wx3;
        ak1 += x1.x*wx0 + x1.y*wx1 + x1.z*wx2 + x1.w*wx3;
        ak2 += x2.x*wx0 + x2.y*wx1 + x2.z*wx2 + x2.w*wx3;
        ak3 += x3.x*wx0 + x3.y*wx1 + x3.z*wx2 + x3.w*wx3;
    }
    const float bhv = bh[u];
    const int r = row0 + rb;
    g_q [(r+0)*UU+u] = aq0;      g_q [(r+1)*UU+u] = aq1;
    g_q [(r+2)*UU+u] = aq2;      g_q [(r+3)*UU+u] = aq3;
    g_kb[(r+0)*UU+u] = ak0+bhv;  g_kb[(r+1)*UU+u] = ak1+bhv;
    g_kb[(r+2)*UU+u] = ak2+bhv;  g_kb[(r+3)*UU+u] = ak3+bhv;
}

// ---------------------------------------------------------------------------
// Kernel 2: windowed attention. grid (L/16, B) = 256 blocks, 256 thr.
// Warp w owns queries 2w, 2w+1; lane l batch-loads kb rows c0=2w+l, c1=c0+32
// into registers (MLP 16), shared by both queries; q1 orphan row 2w+64 via
// u-parallel warp reduction folded into its softmax.
// PDL: stages xs/was before cudaGridDependencySynchronize().
// smem: xs[80][128] | kbs[80][36] | qs[16][32] | was[32] | Aw[8][132]
// ---------------------------------------------------------------------------
#define KBS  36
#define OFF_KBS  (CW*DD)                   // 10240
#define OFF_QS   (OFF_KBS + CW*KBS)        // 13120
#define OFF_WAS  (OFF_QS + TI*UU)          // 13632
#define OFF_AW   (OFF_WAS + UU)            // 13664
#define SMEM_FLOATS (OFF_AW + 8*132)       // 14720 floats = 58880 B

extern __shared__ float smem[];

__global__ __launch_bounds__(256, 2) void attn_kernel(
        const float* __restrict__ x,
        const float* __restrict__ Wa,
        float* __restrict__ out)
{
    float* xs  = smem;
    float* kbs = smem + OFF_KBS;
    float* qs  = smem + OFF_QS;
    float* was = smem + OFF_WAS;
    float* Aw  = smem + OFF_AW;

    const int t    = threadIdx.x;
    const int i0   = blockIdx.x * TI;
    const int base = blockIdx.y * LSEQ;

    // ---- phase 1 (qk-independent): stage xs[80][128] f4 and was ----
    {
        float4* xs4 = (float4*)xs;
        const float4* xg4 = (const float4*)x;
        #pragma unroll
        for (int i = 0; i < 10; i++){
            const int idx = t + i*256;            // [0,2560) f4 of [80][32]
            const int c = idx >> 5, dq = idx & 31;
            const int j = i0 - 32 + c;
            float4 v = make_float4(0.f,0.f,0.f,0.f);
            if (j >= 0 && j < LSEQ) v = xg4[(base + j)*32 + dq];
            xs4[c*32 + dq] = v;
        }
        if (t < 32) was[t] = Wa[t];
    }

    // ---- wait for qk_kernel to fully complete (memory visible) ----
    cudaGridDependencySynchronize();

    // ---- phase 2: stage kbs[80][36] f4 and qs[16][32] from qk output ----
    {
        const float4* kg4 = (const float4*)g_kb;
        #pragma unroll
        for (int i = 0; i < 3; i++){
            const int idx = t + i*256;            // [0,640) f4 of [80][8]
            if (idx < 640){
                const int c = idx >> 3, u4 = idx & 7;
                const int j = i0 - 32 + c;
                float4 v = make_float4(0.f,0.f,0.f,0.f);
                if (j >= 0 && j < LSEQ) v = kg4[(base + j)*8 + u4];
                ((float4*)(kbs + c*KBS))[u4] = v;
            }
        }
        if (t < 128) ((float4*)qs)[t] = ((const float4*)(g_q + (base+i0)*UU))[t];
    }
    __syncthreads();

    const int w = t >> 5;
    const int l = t & 31;
    const int c0 = 2*w + l, c1 = c0 + 32;

    // ---- batch-load the lane's full kb working set (16 indep LDS.128) ----
    float4 kA[8], kB[8];
    {
        const float4* kAp = (const float4*)(kbs + c0*KBS);
        const float4* kBp = (const float4*)(kbs + c1*KBS);
        #pragma unroll
        for (int u4 = 0; u4 < 8; u4++) kA[u4] = kAp[u4];
        #pragma unroll
        for (int u4 = 0; u4 < 8; u4++) kB[u4] = kBp[u4];
    }

    // ---- logits: kA/kB in registers, shared by q0 and q1 ----
    float e0a = 0.f, e0b = 0.f, e1a = 0.f, e1b = 0.f;
    {
        const float4* q0p = (const float4*)(qs + 2*w*UU);
        const float4* q1p = q0p + 8;
        const float4* wap = (const float4*)was;
        #pragma unroll
        for (int u4 = 0; u4 < 8; u4++){
            const float4 wa = wap[u4];            // broadcast
            const float4 q0 = q0p[u4];            // broadcast
            const float4 q1 = q1p[u4];
            e0a += wa.x*fast_tanh(q0.x+kA[u4].x) + wa.y*fast_tanh(q0.y+kA[u4].y)
                 + wa.z*fast_tanh(q0.z+kA[u4].z) + wa.w*fast_tanh(q0.w+kA[u4].w);
            e0b += wa.x*fast_tanh(q0.x+kB[u4].x) + wa.y*fast_tanh(q0.y+kB[u4].y)
                 + wa.z*fast_tanh(q0.z+kB[u4].z) + wa.w*fast_tanh(q0.w+kB[u4].w);
            e1a += wa.x*fast_tanh(q1.x+kA[u4].x) + wa.y*fast_tanh(q1.y+kA[u4].y)
                 + wa.z*fast_tanh(q1.z+kA[u4].z) + wa.w*fast_tanh(q1.w+kA[u4].w);
            e1b += wa.x*fast_tanh(q1.x+kB[u4].x) + wa.y*fast_tanh(q1.y+kB[u4].y)
                 + wa.z*fast_tanh(q1.z+kB[u4].z) + wa.w*fast_tanh(q1.w+kB[u4].w);
        }
    }

    // ---- orphan row 2w+64 for q1: u-parallel (lane = unit) ----
    float eo;
    {
        const float pv = was[l] * fast_tanh(qs[(2*w+1)*UU + l]
                                          + kbs[(2*w+64)*KBS + l]);
        eo = pv;
        #pragma unroll
        for (int o = 16; o; o >>= 1) eo += __shfl_xor_sync(0xffffffffu, eo, o);
        if (i0 + 2*w + 32 >= LSEQ) eo = -1e30f;   // warp-uniform mask
    }

    // ---- masks ----
    {
        const int j0 = i0 - 32 + c0;              // kA row's key index
        if (j0 < 0){ e0a = -1e30f; e1a = -1e30f; }
        if (j0 + 32 >= LSEQ){ e0b = -1e30f; e1b = -1e30f; }
        if (l == 0) e1a = -1e30f;                 // row 2w not in q1 window
    }

    // ---- two warp softmaxes (q1 includes orphan term) ----
    float a0a, a0b, a1a, a1b, ao;
    {
        float m0 = fmaxf(e0a, e0b), m1 = fmaxf(e1a, e1b);
        #pragma unroll
        for (int o = 16; o; o >>= 1){
            m0 = fmaxf(m0, __shfl_xor_sync(0xffffffffu, m0, o));
            m1 = fmaxf(m1, __shfl_xor_sync(0xffffffffu, m1, o));
        }
        const float M1 = fmaxf(m1, eo);
        const float w0a = __expf(e0a - m0), w0b = __expf(e0b - m0);
        const float w1a = __expf(e1a - M1), w1b = __expf(e1b - M1);
        float s0 = w0a + w0b, s1 = w1a + w1b;
        #pragma unroll
        for (int o = 16; o; o >>= 1){
            s0 += __shfl_xor_sync(0xffffffffu, s0, o);
            s1 += __shfl_xor_sync(0xffffffffu, s1, o);
        }
        const float wo = __expf(eo - M1);         // warp-uniform
        const float inv0 = 1.f / (s0 + 1e-7f);
        const float inv1 = 1.f / ((s1 + wo) + 1e-7f);
        a0a = w0a*inv0; a0b = w0b*inv0;
        a1a = w1a*inv1; a1b = w1b*inv1; ao = wo*inv1;
    }

    // ---- publish: slot k <-> row 2w+k ; (.x=q0, .y=q1) ----
    float* A = Aw + w*132;
    ((float2*)A)[l]      = make_float2(a0a, a1a);   // slots 0..31
    ((float2*)A)[l + 32] = make_float2(a0b, a1b);   // slots 32..63
    if (l == 0) ((float2*)A)[64] = make_float2(0.f, ao);   // orphan slot
    __syncwarp();

    // ---- AV: 4 keys per chunk, 6 batched LDS.128 per 32 FFMA ----
    {
        const float4* xs4 = (const float4*)xs;
        const float4* A4  = (const float4*)A;     // pair j = slots 2j, 2j+1
        float4 acc0 = make_float4(0.f,0.f,0.f,0.f);
        float4 acc1 = make_float4(0.f,0.f,0.f,0.f);
        const int rb = 2*w;
        #pragma unroll
        for (int j = 0; j < 32; j += 2){
            const float4 ab0 = A4[j];                      // batched loads
            const float4 ab1 = A4[j+1];
            const float4 xv0 = xs4[(rb + 2*j    )*32 + l];
            const float4 xv1 = xs4[(rb + 2*j + 1)*32 + l];
            const float4 xv2 = xs4[(rb + 2*j + 2)*32 + l];
            const float4 xv3 = xs4[(rb + 2*j + 3)*32 + l];
            acc0.x += ab0.x*xv0.x; acc0.y += ab0.x*xv0.y;
            acc0.z += ab0.x*xv0.z; acc0.w += ab0.x*xv0.w;
            acc1.x += ab0.y*xv0.x; acc1.y += ab0.y*xv0.y;
            acc1.z += ab0.y*xv0.z; acc1.w += ab0.y*xv0.w;
            acc0.x += ab0.z*xv1.x; acc0.y += ab0.z*xv1.y;
            acc0.z += ab0.z*xv1.z; acc0.w += ab0.z*xv1.w;
            acc1.x += ab0.w*xv1.x; acc1.y += ab0.w*xv1.y;
            acc1.z += ab0.w*xv1.z; acc1.w += ab0.w*xv1.w;
            acc0.x += ab1.x*xv2.x; acc0.y += ab1.x*xv2.y;
            acc0.z += ab1.x*xv2.z; acc0.w += ab1.x*xv2.w;
            acc1.x += ab1.y*xv2.x; acc1.y += ab1.y*xv2.y;
            acc1.z += ab1.y*xv2.z; acc1.w += ab1.y*xv2.w;
            acc0.x += ab1.z*xv3.x; acc0.y += ab1.z*xv3.y;
            acc0.z += ab1.z*xv3.z; acc0.w += ab1.z*xv3.w;
            acc1.x += ab1.w*xv3.x; acc1.y += ab1.w*xv3.y;
            acc1.z += ab1.w*xv3.z; acc1.w += ab1.w*xv3.w;
        }
        {   // orphan key (row 2w+64): q1 only
            const float aov = A[129];                    // slot 64 .y
            const float4 xvo = xs4[(rb + 64)*32 + l];
            acc1.x += aov*xvo.x; acc1.y += aov*xvo.y;
            acc1.z += aov*xvo.z; acc1.w += aov*xvo.w;
        }
        float4* out4 = (float4*)out;
        out4[(base + i0 + rb    )*32 + l] = acc0;
        out4[(base + i0 + rb + 1)*32 + l] = acc1;
    }
}

// ---------------------------------------------------------------------------
extern "C" void kernel_launch(void* const* d_in, const int* in_sizes, int n_in,
                              void* d_out, int out_size)
{
    const float* x  = (const float*)d_in[0];
    const float* Wt = (const float*)d_in[1];
    const float* Wx = (const float*)d_in[2];
    const float* bh = (const float*)d_in[3];
    const float* Wa = (const float*)d_in[4];
    // d_in[5] = ba : cancels exactly in the shifted softmax -> unused
    float* out = (float*)d_out;

    qk_kernel<<<NROWS/QK_RPB, 128>>>(x, Wt, Wx, bh);

    cudaFuncSetAttribute(attn_kernel,
                         cudaFuncAttributeMaxDynamicSharedMemorySize,
                         SMEM_FLOATS*4 + 256);

    // PDL launch: attn may start its prologue while qk runs; the
    // cudaGridDependencySynchronize() inside orders the g_q/g_kb reads.
    cudaLaunchConfig_t cfg = {};
    cfg.gridDim  = dim3(LSEQ/TI, BB, 1);
    cfg.blockDim = dim3(256, 1, 1);
    cfg.dynamicSmemBytes = SMEM_FLOATS*4;
    cfg.stream = 0;
    cudaLaunchAttribute at[1];
    at[0].id = cudaLaunchAttributeProgrammaticStreamSerialization;
    at[0].val.programmaticStreamSerializationAllowed = 1;
    cfg.attrs = at;
    cfg.numAttrs = 1;
    cudaLaunchKernelEx(&cfg, attn_kernel, x, Wa, out);
}